// round 2
// baseline (speedup 1.0000x reference)
#include <cuda_runtime.h>

#define D     256
#define NDAY  7
#define NT    288
#define NC    (NDAY * NT)      // 2016 distinct (day, tod) combos
#define ROWS  (64 * 2048)      // B * S = 131072
#define MTILE 16               // combos per CTA in build_table

// Scratch: precomputed output row per (day,tod) combo. 2016*256*4 = ~2 MB.
__device__ float g_table[NC * D];
// TE dtype flag: 1 = int64 layout, 0 = int32 layout.
__device__ int   g_te_is64;

// -------------------------------------------------------------------------
// Kernel 0: detect whether TE is stored as int64 or int32.
// Reads first 512 bytes (safe under both interpretations: int32 buffer is
// 1 MB). Values are 0..287, so under int64 layout the high 32 bits of every
// 64-bit word are zero; under int32 layout the high word is a random tod
// value (P(all 64 zero) = (1/288)^64 ~ 0).
// -------------------------------------------------------------------------
__global__ void detect_te_dtype(const unsigned long long* __restrict__ TE)
{
    unsigned long long acc = 0;
    #pragma unroll
    for (int i = 0; i < 64; i++) acc |= (TE[i] >> 32);
    g_te_is64 = (acc == 0ULL) ? 1 : 0;
}

// -------------------------------------------------------------------------
// Kernel 1: table[c] = relu(W1[day] + W1[7+tod] + b1) @ W2 + b2
// 126 CTAs x 256 threads. Thread = output column e; accumulates MTILE combo
// rows in registers. h tile in shared; h_sh[m][k] reads are warp-uniform
// broadcasts (conflict-free).
// -------------------------------------------------------------------------
__global__ void __launch_bounds__(256) build_table(
    const float* __restrict__ W1, const float* __restrict__ b1,
    const float* __restrict__ W2, const float* __restrict__ b2)
{
    __shared__ float h_sh[MTILE][D];

    const int tid = threadIdx.x;            // 0..255
    const int c0  = blockIdx.x * MTILE;     // base combo index

    #pragma unroll
    for (int m = 0; m < MTILE; m++) {
        int c   = c0 + m;
        int day = c / NT;
        int tod = c - day * NT;
        float v = W1[day * D + tid] + W1[(NDAY + tod) * D + tid] + b1[tid];
        h_sh[m][tid] = fmaxf(v, 0.0f);
    }
    __syncthreads();

    const int e = tid;
    float acc[MTILE];
    const float bias = b2[e];
    #pragma unroll
    for (int m = 0; m < MTILE; m++) acc[m] = bias;

    #pragma unroll 4
    for (int k = 0; k < D; k += 4) {
        float w0  = W2[(k + 0) * D + e];
        float w1v = W2[(k + 1) * D + e];
        float w2v = W2[(k + 2) * D + e];
        float w3v = W2[(k + 3) * D + e];
        #pragma unroll
        for (int m = 0; m < MTILE; m++) {
            float4 h4 = *reinterpret_cast<const float4*>(&h_sh[m][k]);
            acc[m] = fmaf(h4.x, w0,  acc[m]);
            acc[m] = fmaf(h4.y, w1v, acc[m]);
            acc[m] = fmaf(h4.z, w2v, acc[m]);
            acc[m] = fmaf(h4.w, w3v, acc[m]);
        }
    }

    #pragma unroll
    for (int m = 0; m < MTILE; m++)
        g_table[(c0 + m) * D + e] = acc[m];
}

// -------------------------------------------------------------------------
// Kernel 2: out[row] = table[day*NT + tod]. One warp per row, float4 copies.
// Table (2 MB) is L2-resident; output writes stream to DRAM.
// -------------------------------------------------------------------------
__global__ void __launch_bounds__(256) gather_out(
    const void* __restrict__ TEp, float* __restrict__ out)
{
    const int gtid = blockIdx.x * blockDim.x + threadIdx.x;
    const int row  = gtid >> 5;
    const int lane = gtid & 31;
    if (row >= ROWS) return;

    int t0, t1;
    if (g_te_is64) {
        const long long* TE = (const long long*)TEp;
        t0 = (int)TE[(size_t)row * 2 + 0];
        t1 = (int)TE[(size_t)row * 2 + 1];
    } else {
        const int* TE = (const int*)TEp;
        t0 = TE[(size_t)row * 2 + 0];
        t1 = TE[(size_t)row * 2 + 1];
    }

    // Defensive non-negative modulo: even on a mis-detect this cannot fault.
    int day = t0 % NDAY; day += (day >> 31) & NDAY;
    int tod = t1 % NT;   tod += (tod >> 31) & NT;
    int c   = day * NT + tod;

    const float4* __restrict__ src = reinterpret_cast<const float4*>(g_table + (size_t)c * D);
    float4* __restrict__ dst       = reinterpret_cast<float4*>(out + (size_t)row * D);

    dst[lane]      = src[lane];
    dst[lane + 32] = src[lane + 32];
}

// -------------------------------------------------------------------------
// Launch. Inputs resolved by element count (robust to scalar T presence):
//   TE = d_in[0] (262144 elems)
//   W1: 295*256 = 75520   W2: 256*256 = 65536   b1/b2: 256 (order: b1 first)
// -------------------------------------------------------------------------
extern "C" void kernel_launch(void* const* d_in, const int* in_sizes, int n_in,
                              void* d_out, int out_size)
{
    const void* TE = d_in[0];
    const float* W1 = nullptr;
    const float* b1 = nullptr;
    const float* W2 = nullptr;
    const float* b2 = nullptr;

    for (int j = 1; j < n_in; j++) {
        int sz = in_sizes[j];
        if (sz == (NDAY + NT) * D) {
            W1 = (const float*)d_in[j];
        } else if (sz == D * D) {
            W2 = (const float*)d_in[j];
        } else if (sz == D) {
            if (!b1) b1 = (const float*)d_in[j];
            else     b2 = (const float*)d_in[j];
        }
    }
    if (!W1 || !b1 || !W2 || !b2) return;  // fail loudly via rel_err, not a fault

    float* out = (float*)d_out;

    detect_te_dtype<<<1, 1>>>((const unsigned long long*)TE);
    build_table<<<NC / MTILE, 256>>>(W1, b1, W2, b2);
    gather_out<<<(ROWS * 32) / 256, 256>>>(TE, out);
}

// round 3
// speedup vs baseline: 1.0174x; 1.0174x over previous
#include <cuda_runtime.h>

#define D     256
#define NDAY  7
#define NT    288
#define NC    (NDAY * NT)      // 2016 distinct (day, tod) combos
#define ROWS  (64 * 2048)      // B * S = 131072
#define MTILE 16               // combos per CTA in build_table
#define NBLK_TABLE (NC / MTILE)  // 126

#define GATHER_BLOCKS 592      // 4 CTAs/SM * 148 SMs -> exactly one wave
#define GATHER_THREADS 256

// Scratch: precomputed output row per (day,tod) combo. 2016*256*4 = ~2 MB.
__device__ float g_table[NC * D];
// TE dtype flag: 1 = int64 layout, 0 = int32 layout.
__device__ int   g_te_is64;

// -------------------------------------------------------------------------
// Kernel 1: table[c] = relu(W1[day] + W1[7+tod] + b1) @ W2 + b2
// Blocks 0..125: 256 threads, thread = output column e, MTILE combos in regs.
// Block 126: TE dtype detection (1 warp, ballot reduce over first 512 B).
// -------------------------------------------------------------------------
__global__ void __launch_bounds__(256) build_table(
    const float* __restrict__ W1, const float* __restrict__ b1,
    const float* __restrict__ W2, const float* __restrict__ b2,
    const unsigned long long* __restrict__ TE64)
{
    if (blockIdx.x == NBLK_TABLE) {
        // Detection block. Values are 0..287: under int64 layout the high
        // 32 bits of every 64-bit word are zero; under int32 they are a
        // random index (P(all 64 high-words zero) ~ (1/288)^64 ~ 0).
        if (threadIdx.x < 32) {
            int lane = threadIdx.x;
            unsigned long long v = (TE64[lane] >> 32) | (TE64[lane + 32] >> 32);
            unsigned ballot = __ballot_sync(0xffffffffu, v != 0ULL);
            if (lane == 0) g_te_is64 = (ballot == 0u) ? 1 : 0;
        }
        return;
    }

    __shared__ float h_sh[MTILE][D];

    const int tid = threadIdx.x;            // 0..255
    const int c0  = blockIdx.x * MTILE;     // base combo index

    #pragma unroll
    for (int m = 0; m < MTILE; m++) {
        int c   = c0 + m;
        int day = c / NT;
        int tod = c - day * NT;
        float v = W1[day * D + tid] + W1[(NDAY + tod) * D + tid] + b1[tid];
        h_sh[m][tid] = fmaxf(v, 0.0f);
    }
    __syncthreads();

    const int e = tid;
    float acc[MTILE];
    const float bias = b2[e];
    #pragma unroll
    for (int m = 0; m < MTILE; m++) acc[m] = bias;

    #pragma unroll 4
    for (int k = 0; k < D; k += 4) {
        float w0  = W2[(k + 0) * D + e];
        float w1v = W2[(k + 1) * D + e];
        float w2v = W2[(k + 2) * D + e];
        float w3v = W2[(k + 3) * D + e];
        #pragma unroll
        for (int m = 0; m < MTILE; m++) {
            float4 h4 = *reinterpret_cast<const float4*>(&h_sh[m][k]);
            acc[m] = fmaf(h4.x, w0,  acc[m]);
            acc[m] = fmaf(h4.y, w1v, acc[m]);
            acc[m] = fmaf(h4.z, w2v, acc[m]);
            acc[m] = fmaf(h4.w, w3v, acc[m]);
        }
    }

    #pragma unroll
    for (int m = 0; m < MTILE; m++)
        g_table[(c0 + m) * D + e] = acc[m];
}

// -------------------------------------------------------------------------
// Kernel 2: out[row] = table[day*NT + tod].
// Persistent grid-stride: 592 blocks x 8 warps = one wave (32 warps/SM).
// Warp per row, ~28 rows per warp. TE index load for row i+1 is issued
// before copying row i (1-deep software pipeline) to hide DRAM latency.
// -------------------------------------------------------------------------
__global__ void __launch_bounds__(GATHER_THREADS) gather_out(
    const void* __restrict__ TEp, float* __restrict__ out)
{
    const int lane    = threadIdx.x & 31;
    const int warp    = blockIdx.x * (GATHER_THREADS >> 5) + (threadIdx.x >> 5);
    const int n_warps = GATHER_BLOCKS * (GATHER_THREADS >> 5);
    const bool is64   = (g_te_is64 != 0);

    const longlong2* __restrict__ TE8 = (const longlong2*)TEp;
    const int2*      __restrict__ TE4 = (const int2*)TEp;

    int row = warp;
    if (row >= ROWS) return;

    // Prime the pipeline: load indices for the first row.
    int t0, t1;
    if (is64) { longlong2 te = TE8[row]; t0 = (int)te.x; t1 = (int)te.y; }
    else      { int2      te = TE4[row]; t0 = te.x;      t1 = te.y;      }

    while (true) {
        int next = row + n_warps;
        int n0 = 0, n1 = 0;
        if (next < ROWS) {
            if (is64) { longlong2 te = TE8[next]; n0 = (int)te.x; n1 = (int)te.y; }
            else      { int2      te = TE4[next]; n0 = te.x;      n1 = te.y;      }
        }

        // Defensive non-negative modulo: cannot fault even on mis-detect.
        int day = t0 % NDAY; day += (day >> 31) & NDAY;
        int tod = t1 % NT;   tod += (tod >> 31) & NT;
        int c   = day * NT + tod;

        const float4* __restrict__ src =
            reinterpret_cast<const float4*>(g_table + (size_t)c * D);
        float4* __restrict__ dst =
            reinterpret_cast<float4*>(out + (size_t)row * D);

        // 256 floats = 64 float4; 32 lanes x 2 (independent -> MLP 2).
        float4 v0 = src[lane];
        float4 v1 = src[lane + 32];
        dst[lane]      = v0;
        dst[lane + 32] = v1;

        if (next >= ROWS) break;
        row = next; t0 = n0; t1 = n1;
    }
}

// -------------------------------------------------------------------------
// Launch. Inputs resolved by element count (robust to scalar T presence):
//   TE = d_in[0] (262144 elems)
//   W1: 295*256 = 75520   W2: 256*256 = 65536   b1/b2: 256 (order: b1 first)
// -------------------------------------------------------------------------
extern "C" void kernel_launch(void* const* d_in, const int* in_sizes, int n_in,
                              void* d_out, int out_size)
{
    const void* TE = d_in[0];
    const float* W1 = nullptr;
    const float* b1 = nullptr;
    const float* W2 = nullptr;
    const float* b2 = nullptr;

    for (int j = 1; j < n_in; j++) {
        int sz = in_sizes[j];
        if (sz == (NDAY + NT) * D) {
            W1 = (const float*)d_in[j];
        } else if (sz == D * D) {
            W2 = (const float*)d_in[j];
        } else if (sz == D) {
            if (!b1) b1 = (const float*)d_in[j];
            else     b2 = (const float*)d_in[j];
        }
    }
    if (!W1 || !b1 || !W2 || !b2) return;

    float* out = (float*)d_out;

    build_table<<<NBLK_TABLE + 1, 256>>>(W1, b1, W2, b2,
                                         (const unsigned long long*)TE);
    gather_out<<<GATHER_BLOCKS, GATHER_THREADS>>>(TE, out);
}

// round 4
// speedup vs baseline: 1.7545x; 1.7245x over previous
#include <cuda_runtime.h>

#define D      256
#define NDAY   7
#define NT     288
#define NC     (NDAY * NT)        // 2016 distinct (day, tod) combos
#define ROWS   (64 * 2048)        // B * S = 131072
#define MTILE  16                 // combos per m-block
#define NMB    (NC / MTILE)       // 126 m-blocks
#define KSPLIT 4                  // k-quarters
#define KQ     (D / KSPLIT)       // 64 k-values per CTA
#define NBLK_BUILD (NMB * KSPLIT) // 504

#define GATHER_BLOCKS  592        // 4 CTAs/SM * 148 SMs
#define GATHER_THREADS 256

// Final table: one output row per (day,tod) combo. ~2 MB.
__device__ float g_table[NC * D];
// K-split partial sums. 4 x 2 MB.
__device__ float g_part[KSPLIT][NC * D];
// TE dtype flag: 1 = int64 layout, 0 = int32 layout.
__device__ int   g_te_is64;

// -------------------------------------------------------------------------
// Kernel 1: partial[ks][c][e] = sum_{k in quarter ks} relu_h[c][k] * W2[k][e]
//           (+ b2[e] folded into quarter 0)
// Grid: 126 m-blocks x 4 k-quarters = 504 CTAs, 256 threads.
// Block 504: TE dtype detection.
// -------------------------------------------------------------------------
__global__ void __launch_bounds__(256) build_partial(
    const float* __restrict__ W1, const float* __restrict__ b1,
    const float* __restrict__ W2, const float* __restrict__ b2,
    const unsigned long long* __restrict__ TE64)
{
    const int bx = blockIdx.x;
    if (bx == NBLK_BUILD) {
        // TE values are 0..287: under int64 layout every high 32-bit word is
        // zero; under int32 it is a random index. P(false int64) ~ (1/288)^64.
        if (threadIdx.x < 32) {
            int lane = threadIdx.x;
            unsigned long long v = (TE64[lane] >> 32) | (TE64[lane + 32] >> 32);
            unsigned ballot = __ballot_sync(0xffffffffu, v != 0ULL);
            if (lane == 0) g_te_is64 = (ballot == 0u) ? 1 : 0;
        }
        return;
    }

    const int mb = bx >> 2;        // m-block 0..125
    const int ks = bx & 3;         // k-quarter 0..3
    const int c0 = mb * MTILE;
    const int k0 = ks * KQ;
    const int tid = threadIdx.x;

    __shared__ float h_sh[MTILE][KQ];   // 16 x 64 x 4B = 4 KB

    // Phase 1: h slice for this k-quarter. 16*64 = 1024 values, 256 threads.
    #pragma unroll
    for (int it = 0; it < (MTILE * KQ) / 256; it++) {
        int idx = it * 256 + tid;
        int m   = idx >> 6;            // /KQ
        int kk  = idx & (KQ - 1);
        int c   = c0 + m;
        int day = c / NT;
        int tod = c - day * NT;
        int k   = k0 + kk;
        float v = W1[day * D + k] + W1[(NDAY + tod) * D + k] + b1[k];
        h_sh[m][kk] = fmaxf(v, 0.0f);
    }
    __syncthreads();

    // Phase 2: partial GEMM over this k-quarter. Thread = output column e.
    const int e = tid;
    float acc[MTILE];
    const float init = (ks == 0) ? b2[e] : 0.0f;
    #pragma unroll
    for (int m = 0; m < MTILE; m++) acc[m] = init;

    #pragma unroll 4
    for (int kk = 0; kk < KQ; kk += 4) {
        float w0 = W2[(k0 + kk + 0) * D + e];
        float w1 = W2[(k0 + kk + 1) * D + e];
        float w2 = W2[(k0 + kk + 2) * D + e];
        float w3 = W2[(k0 + kk + 3) * D + e];
        #pragma unroll
        for (int m = 0; m < MTILE; m++) {
            float4 h4 = *reinterpret_cast<const float4*>(&h_sh[m][kk]);
            acc[m] = fmaf(h4.x, w0, acc[m]);
            acc[m] = fmaf(h4.y, w1, acc[m]);
            acc[m] = fmaf(h4.z, w2, acc[m]);
            acc[m] = fmaf(h4.w, w3, acc[m]);
        }
    }

    float* __restrict__ part = g_part[ks];
    #pragma unroll
    for (int m = 0; m < MTILE; m++)
        part[(c0 + m) * D + e] = acc[m];
}

// -------------------------------------------------------------------------
// Kernel 2: g_table = sum of 4 partials. 2016*256 floats = 129024 float4,
// exactly 504 blocks x 256 threads x 1 float4.
// -------------------------------------------------------------------------
__global__ void __launch_bounds__(256) reduce_parts()
{
    int i = blockIdx.x * 256 + threadIdx.x;
    const float4* p0 = reinterpret_cast<const float4*>(g_part[0]);
    const float4* p1 = reinterpret_cast<const float4*>(g_part[1]);
    const float4* p2 = reinterpret_cast<const float4*>(g_part[2]);
    const float4* p3 = reinterpret_cast<const float4*>(g_part[3]);
    float4 a = p0[i], b = p1[i], c = p2[i], d = p3[i];
    float4 r;
    r.x = (a.x + b.x) + (c.x + d.x);
    r.y = (a.y + b.y) + (c.y + d.y);
    r.z = (a.z + b.z) + (c.z + d.z);
    r.w = (a.w + b.w) + (c.w + d.w);
    reinterpret_cast<float4*>(g_table)[i] = r;
}

// -------------------------------------------------------------------------
// Kernel 3: out[row] = table[day*NT + tod]. Persistent, one warp per row.
// Streaming stores keep the 134 MB output from churning L2 against the
// hot 2 MB table.
// -------------------------------------------------------------------------
__global__ void __launch_bounds__(GATHER_THREADS) gather_out(
    const void* __restrict__ TEp, float* __restrict__ out)
{
    const int lane    = threadIdx.x & 31;
    const int warp    = blockIdx.x * (GATHER_THREADS >> 5) + (threadIdx.x >> 5);
    const int n_warps = GATHER_BLOCKS * (GATHER_THREADS >> 5);
    const bool is64   = (g_te_is64 != 0);

    const longlong2* __restrict__ TE8 = (const longlong2*)TEp;
    const int2*      __restrict__ TE4 = (const int2*)TEp;

    int row = warp;
    if (row >= ROWS) return;

    int t0, t1;
    if (is64) { longlong2 te = TE8[row]; t0 = (int)te.x; t1 = (int)te.y; }
    else      { int2      te = TE4[row]; t0 = te.x;      t1 = te.y;      }

    while (true) {
        int next = row + n_warps;
        int n0 = 0, n1 = 0;
        if (next < ROWS) {
            if (is64) { longlong2 te = TE8[next]; n0 = (int)te.x; n1 = (int)te.y; }
            else      { int2      te = TE4[next]; n0 = te.x;      n1 = te.y;      }
        }

        int day = t0 % NDAY; day += (day >> 31) & NDAY;
        int tod = t1 % NT;   tod += (tod >> 31) & NT;
        int c   = day * NT + tod;

        const float4* __restrict__ src =
            reinterpret_cast<const float4*>(g_table + (size_t)c * D);
        float4* __restrict__ dst =
            reinterpret_cast<float4*>(out + (size_t)row * D);

        float4 v0 = src[lane];
        float4 v1 = src[lane + 32];
        __stcs(dst + lane,      v0);
        __stcs(dst + lane + 32, v1);

        if (next >= ROWS) break;
        row = next; t0 = n0; t1 = n1;
    }
}

// -------------------------------------------------------------------------
// Launch. Inputs resolved by element count:
//   TE = d_in[0]; W1: 295*256 = 75520; W2: 256*256 = 65536; b1/b2: 256 each.
// -------------------------------------------------------------------------
extern "C" void kernel_launch(void* const* d_in, const int* in_sizes, int n_in,
                              void* d_out, int out_size)
{
    const void* TE = d_in[0];
    const float* W1 = nullptr;
    const float* b1 = nullptr;
    const float* W2 = nullptr;
    const float* b2 = nullptr;

    for (int j = 1; j < n_in; j++) {
        int sz = in_sizes[j];
        if (sz == (NDAY + NT) * D) {
            W1 = (const float*)d_in[j];
        } else if (sz == D * D) {
            W2 = (const float*)d_in[j];
        } else if (sz == D) {
            if (!b1) b1 = (const float*)d_in[j];
            else     b2 = (const float*)d_in[j];
        }
    }
    if (!W1 || !b1 || !W2 || !b2) return;

    float* out = (float*)d_out;

    build_partial<<<NBLK_BUILD + 1, 256>>>(W1, b1, W2, b2,
                                           (const unsigned long long*)TE);
    reduce_parts<<<NBLK_BUILD, 256>>>();
    gather_out<<<GATHER_BLOCKS, GATHER_THREADS>>>(TE, out);
}

// round 5
// speedup vs baseline: 1.7587x; 1.0024x over previous
#include <cuda_runtime.h>

#define D      256
#define NDAY   7
#define NT     288
#define NC     (NDAY * NT)        // 2016 distinct (day, tod) combos
#define ROWS   (64 * 2048)        // B * S = 131072
#define MTILE  16                 // combos per m-block
#define NMB    (NC / MTILE)       // 126 m-blocks
#define KSPLIT 4                  // k-quarters
#define KQ     (D / KSPLIT)       // 64 k-values per CTA
#define NBLK_BUILD (NMB * KSPLIT) // 504
#define MPT    (MTILE / 2)        // 8 combos per thread (2 halves)

#define GATHER_BLOCKS  592        // 4 CTAs/SM * 148 SMs
#define GATHER_THREADS 256

// Final table: one output row per (day,tod) combo. ~2 MB.
__device__ float g_table[NC * D];
// K-split partial sums. 4 x 2 MB.
__device__ float g_part[KSPLIT][NC * D];
// TE dtype flag: 1 = int64 layout, 0 = int32 layout.
__device__ int   g_te_is64;

// -------------------------------------------------------------------------
// Kernel 1: partial[ks][c][e] = sum_{k in quarter ks} relu_h[c][k] * W2[k][e]
//           (+ b2[e] folded into quarter 0)
// Grid: 126 m-blocks x 4 k-quarters = 504 CTAs, 256 threads.
// Thread layout: e = tid & 127 -> computes columns e and e+128;
//                half = tid >> 7 -> owns combos [half*8, half*8+8).
// Each h4 LDS.128 feeds 8 FMAs (2 cols x 4 k) => LDS/SM balanced vs FMA floor.
// Block 504: TE dtype detection.
// -------------------------------------------------------------------------
__global__ void __launch_bounds__(256) build_partial(
    const float* __restrict__ W1, const float* __restrict__ b1,
    const float* __restrict__ W2, const float* __restrict__ b2,
    const unsigned long long* __restrict__ TE64)
{
    const int bx = blockIdx.x;
    if (bx == NBLK_BUILD) {
        // TE values are 0..287: under int64 layout every high 32-bit word is
        // zero; under int32 it is a random index. P(false int64) ~ (1/288)^64.
        if (threadIdx.x < 32) {
            int lane = threadIdx.x;
            unsigned long long v = (TE64[lane] >> 32) | (TE64[lane + 32] >> 32);
            unsigned ballot = __ballot_sync(0xffffffffu, v != 0ULL);
            if (lane == 0) g_te_is64 = (ballot == 0u) ? 1 : 0;
        }
        return;
    }

    const int mb = bx >> 2;        // m-block 0..125
    const int ks = bx & 3;         // k-quarter 0..3
    const int c0 = mb * MTILE;
    const int k0 = ks * KQ;
    const int tid = threadIdx.x;

    __shared__ float h_sh[MTILE][KQ];   // 16 x 64 x 4B = 4 KB

    // Phase 1: h slice for this k-quarter. 16*64 = 1024 values, 256 threads.
    #pragma unroll
    for (int it = 0; it < (MTILE * KQ) / 256; it++) {
        int idx = it * 256 + tid;
        int m   = idx >> 6;            // /KQ
        int kk  = idx & (KQ - 1);
        int c   = c0 + m;
        int day = c / NT;
        int tod = c - day * NT;
        int k   = k0 + kk;
        float v = W1[day * D + k] + W1[(NDAY + tod) * D + k] + b1[k];
        h_sh[m][kk] = fmaxf(v, 0.0f);
    }
    __syncthreads();

    // Phase 2: partial GEMM. Thread -> columns (e, e+128), combos m0..m0+7.
    const int e    = tid & 127;
    const int half = tid >> 7;          // warps 0-3 -> 0, warps 4-7 -> 1
    const int m0   = half * MPT;

    float acc0[MPT];   // column e
    float acc1[MPT];   // column e + 128
    const float i0 = (ks == 0) ? b2[e]       : 0.0f;
    const float i1 = (ks == 0) ? b2[e + 128] : 0.0f;
    #pragma unroll
    for (int m = 0; m < MPT; m++) { acc0[m] = i0; acc1[m] = i1; }

    #pragma unroll 4
    for (int kk = 0; kk < KQ; kk += 4) {
        const float* w = W2 + (size_t)(k0 + kk) * D + e;
        float wa0 = w[0 * D],       wa1 = w[1 * D];
        float wa2 = w[2 * D],       wa3 = w[3 * D];
        float wb0 = w[0 * D + 128], wb1 = w[1 * D + 128];
        float wb2 = w[2 * D + 128], wb3 = w[3 * D + 128];
        #pragma unroll
        for (int m = 0; m < MPT; m++) {
            float4 h4 = *reinterpret_cast<const float4*>(&h_sh[m0 + m][kk]);
            acc0[m] = fmaf(h4.x, wa0, acc0[m]);
            acc0[m] = fmaf(h4.y, wa1, acc0[m]);
            acc0[m] = fmaf(h4.z, wa2, acc0[m]);
            acc0[m] = fmaf(h4.w, wa3, acc0[m]);
            acc1[m] = fmaf(h4.x, wb0, acc1[m]);
            acc1[m] = fmaf(h4.y, wb1, acc1[m]);
            acc1[m] = fmaf(h4.z, wb2, acc1[m]);
            acc1[m] = fmaf(h4.w, wb3, acc1[m]);
        }
    }

    float* __restrict__ part = g_part[ks];
    #pragma unroll
    for (int m = 0; m < MPT; m++) {
        part[(size_t)(c0 + m0 + m) * D + e]       = acc0[m];
        part[(size_t)(c0 + m0 + m) * D + e + 128] = acc1[m];
    }
}

// -------------------------------------------------------------------------
// Kernel 2: g_table = sum of 4 partials. 129024 float4 = 504 x 256 x 1.
// -------------------------------------------------------------------------
__global__ void __launch_bounds__(256) reduce_parts()
{
    int i = blockIdx.x * 256 + threadIdx.x;
    const float4* p0 = reinterpret_cast<const float4*>(g_part[0]);
    const float4* p1 = reinterpret_cast<const float4*>(g_part[1]);
    const float4* p2 = reinterpret_cast<const float4*>(g_part[2]);
    const float4* p3 = reinterpret_cast<const float4*>(g_part[3]);
    float4 a = p0[i], b = p1[i], c = p2[i], d = p3[i];
    float4 r;
    r.x = (a.x + b.x) + (c.x + d.x);
    r.y = (a.y + b.y) + (c.y + d.y);
    r.z = (a.z + b.z) + (c.z + d.z);
    r.w = (a.w + b.w) + (c.w + d.w);
    reinterpret_cast<float4*>(g_table)[i] = r;
}

// -------------------------------------------------------------------------
// Kernel 3: out[row] = table[day*NT + tod]. Persistent, one warp per row.
// Streaming stores keep the 134 MB output from churning L2 against the
// hot 2 MB table.
// -------------------------------------------------------------------------
__global__ void __launch_bounds__(GATHER_THREADS) gather_out(
    const void* __restrict__ TEp, float* __restrict__ out)
{
    const int lane    = threadIdx.x & 31;
    const int warp    = blockIdx.x * (GATHER_THREADS >> 5) + (threadIdx.x >> 5);
    const int n_warps = GATHER_BLOCKS * (GATHER_THREADS >> 5);
    const bool is64   = (g_te_is64 != 0);

    const longlong2* __restrict__ TE8 = (const longlong2*)TEp;
    const int2*      __restrict__ TE4 = (const int2*)TEp;

    int row = warp;
    if (row >= ROWS) return;

    int t0, t1;
    if (is64) { longlong2 te = TE8[row]; t0 = (int)te.x; t1 = (int)te.y; }
    else      { int2      te = TE4[row]; t0 = te.x;      t1 = te.y;      }

    while (true) {
        int next = row + n_warps;
        int n0 = 0, n1 = 0;
        if (next < ROWS) {
            if (is64) { longlong2 te = TE8[next]; n0 = (int)te.x; n1 = (int)te.y; }
            else      { int2      te = TE4[next]; n0 = te.x;      n1 = te.y;      }
        }

        int day = t0 % NDAY; day += (day >> 31) & NDAY;
        int tod = t1 % NT;   tod += (tod >> 31) & NT;
        int c   = day * NT + tod;

        const float4* __restrict__ src =
            reinterpret_cast<const float4*>(g_table + (size_t)c * D);
        float4* __restrict__ dst =
            reinterpret_cast<float4*>(out + (size_t)row * D);

        float4 v0 = src[lane];
        float4 v1 = src[lane + 32];
        __stcs(dst + lane,      v0);
        __stcs(dst + lane + 32, v1);

        if (next >= ROWS) break;
        row = next; t0 = n0; t1 = n1;
    }
}

// -------------------------------------------------------------------------
// Launch. Inputs resolved by element count:
//   TE = d_in[0]; W1: 295*256 = 75520; W2: 256*256 = 65536; b1/b2: 256 each.
// -------------------------------------------------------------------------
extern "C" void kernel_launch(void* const* d_in, const int* in_sizes, int n_in,
                              void* d_out, int out_size)
{
    const void* TE = d_in[0];
    const float* W1 = nullptr;
    const float* b1 = nullptr;
    const float* W2 = nullptr;
    const float* b2 = nullptr;

    for (int j = 1; j < n_in; j++) {
        int sz = in_sizes[j];
        if (sz == (NDAY + NT) * D) {
            W1 = (const float*)d_in[j];
        } else if (sz == D * D) {
            W2 = (const float*)d_in[j];
        } else if (sz == D) {
            if (!b1) b1 = (const float*)d_in[j];
            else     b2 = (const float*)d_in[j];
        }
    }
    if (!W1 || !b1 || !W2 || !b2) return;

    float* out = (float*)d_out;

    build_partial<<<NBLK_BUILD + 1, 256>>>(W1, b1, W2, b2,
                                           (const unsigned long long*)TE);
    reduce_parts<<<NBLK_BUILD, 256>>>();
    gather_out<<<GATHER_BLOCKS, GATHER_THREADS>>>(TE, out);
}